// round 1
// baseline (speedup 1.0000x reference)
#include <cuda_runtime.h>
#include <math.h>

// Problem constants
#define DD   1024
#define NB   8
#define NS   64          // slots (K in python)
#define NM   4096        // positions (M in python)
#define EPS_F 1e-6f
#define SCALE_F 0.03125f // 1024^-0.5

// ---------------------------------------------------------------------------
// Scratch (static device globals — no cudaMalloc allowed)
// ---------------------------------------------------------------------------
__device__ float g_kproj[(long)NB * NM * DD];        // 128 MB
__device__ float g_vproj[(long)NB * NM * DD];        // 128 MB
__device__ float g_rsP[NB * NM];
__device__ float g_slots[NB * NS * DD];
__device__ float g_rss[NB * NS];
__device__ float g_q[NB * NS * DD];
__device__ float g_scores[(long)NB * NS * NM];       // 8 MB
__device__ float g_updates[NB * NS * DD];
__device__ float g_gx[NB * NS * 3 * DD];
__device__ float g_gh[NB * NS * 3 * DD];

// ---------------------------------------------------------------------------
// Row inverse-RMS: rs[r] = rsqrt(mean(x^2) + eps)
// ---------------------------------------------------------------------------
__global__ void rms_rows(const float* __restrict__ X, float* __restrict__ rs, int d) {
    int r = blockIdx.x;
    const float* x = X + (long)r * d;
    float s = 0.f;
    for (int i = threadIdx.x; i < d; i += blockDim.x) {
        float v = x[i];
        s += v * v;
    }
    __shared__ float red[256];
    red[threadIdx.x] = s;
    __syncthreads();
    for (int off = 128; off > 0; off >>= 1) {
        if (threadIdx.x < off) red[threadIdx.x] += red[threadIdx.x + off];
        __syncthreads();
    }
    if (threadIdx.x == 0) rs[r] = rsqrtf(red[0] / (float)d + EPS_F);
}

// ---------------------------------------------------------------------------
// NT GEMM:  C[m,n] = alpha * sum_c (A[m,c]*rowScale[m]*colScale[c]) * B[n,c] (+bias[n])
// A: M x K row-major, B: N x K row-major. Batched via blockIdx.z strides.
// Requires: K % BK == 0, N % BN == 0 (M guarded).
// ---------------------------------------------------------------------------
template <int BM, int BN, int BK, int TM, int TN>
__global__ __launch_bounds__((BM / TM) * (BN / TN))
void gemm_nt(const float* __restrict__ A, const float* __restrict__ B,
             float* __restrict__ C, int M, int N, int Kd,
             long sA, long sB, long sC,
             const float* __restrict__ rowScale,
             const float* __restrict__ colScale,
             const float* __restrict__ bias, float alpha)
{
    constexpr int THREADS = (BM / TM) * (BN / TN);
    __shared__ float As[BK][BM];
    __shared__ float Bs[BK][BN];

    int tid = threadIdx.x;
    A += blockIdx.z * sA;
    B += blockIdx.z * sB;
    C += blockIdx.z * sC;

    int m0 = blockIdx.y * BM;
    int n0 = blockIdx.x * BN;

    float acc[TM][TN];
#pragma unroll
    for (int i = 0; i < TM; i++)
#pragma unroll
        for (int j = 0; j < TN; j++) acc[i][j] = 0.f;

    int tx = tid % (BN / TN);
    int ty = tid / (BN / TN);

    for (int k0 = 0; k0 < Kd; k0 += BK) {
        // A tile -> As[k][m]
#pragma unroll
        for (int i = 0; i < (BM * BK) / (THREADS * 4); i++) {
            int idx = (tid + i * THREADS) * 4;
            int r = idx / BK, c = idx % BK;
            int gm = m0 + r;
            float4 v = make_float4(0.f, 0.f, 0.f, 0.f);
            if (gm < M) {
                v = *(const float4*)(A + (long)gm * Kd + k0 + c);
                if (rowScale) {
                    float rsv = rowScale[gm];
                    v.x *= rsv; v.y *= rsv; v.z *= rsv; v.w *= rsv;
                }
                if (colScale) {
                    v.x *= colScale[k0 + c + 0];
                    v.y *= colScale[k0 + c + 1];
                    v.z *= colScale[k0 + c + 2];
                    v.w *= colScale[k0 + c + 3];
                }
            }
            As[c + 0][r] = v.x;
            As[c + 1][r] = v.y;
            As[c + 2][r] = v.z;
            As[c + 3][r] = v.w;
        }
        // B tile -> Bs[k][n]
#pragma unroll
        for (int i = 0; i < (BN * BK) / (THREADS * 4); i++) {
            int idx = (tid + i * THREADS) * 4;
            int r = idx / BK, c = idx % BK;
            int gn = n0 + r;
            float4 v = *(const float4*)(B + (long)gn * Kd + k0 + c);
            Bs[c + 0][r] = v.x;
            Bs[c + 1][r] = v.y;
            Bs[c + 2][r] = v.z;
            Bs[c + 3][r] = v.w;
        }
        __syncthreads();

#pragma unroll
        for (int k = 0; k < BK; k++) {
            float ar[TM], br[TN];
#pragma unroll
            for (int i = 0; i < TM; i++) ar[i] = As[k][ty * TM + i];
#pragma unroll
            for (int j = 0; j < TN; j++) br[j] = Bs[k][tx * TN + j];
#pragma unroll
            for (int i = 0; i < TM; i++)
#pragma unroll
                for (int j = 0; j < TN; j++) acc[i][j] += ar[i] * br[j];
        }
        __syncthreads();
    }

#pragma unroll
    for (int i = 0; i < TM; i++) {
        int gm = m0 + ty * TM + i;
        if (gm >= M) continue;
#pragma unroll
        for (int j = 0; j < TN; j++) {
            int gn = n0 + tx * TN + j;
            float v = acc[i][j] * alpha;
            if (bias) v += bias[gn];
            C[(long)gm * N + gn] = v;
        }
    }
}

// ---------------------------------------------------------------------------
// NN GEMM:  C[m,n] = sum_k A[m,k] * B[k,n]
// A: M x K row-major, B: K x N row-major. Batched via blockIdx.z strides.
// Requires: K % BK == 0, N % BN == 0.
// ---------------------------------------------------------------------------
template <int BM, int BN, int BK, int TM, int TN>
__global__ __launch_bounds__((BM / TM) * (BN / TN))
void gemm_nn(const float* __restrict__ A, const float* __restrict__ B,
             float* __restrict__ C, int M, int N, int Kd,
             long sA, long sB, long sC)
{
    constexpr int THREADS = (BM / TM) * (BN / TN);
    __shared__ float As[BK][BM];
    __shared__ float Bs[BK][BN];

    int tid = threadIdx.x;
    A += blockIdx.z * sA;
    B += blockIdx.z * sB;
    C += blockIdx.z * sC;

    int m0 = blockIdx.y * BM;
    int n0 = blockIdx.x * BN;

    float acc[TM][TN];
#pragma unroll
    for (int i = 0; i < TM; i++)
#pragma unroll
        for (int j = 0; j < TN; j++) acc[i][j] = 0.f;

    int tx = tid % (BN / TN);
    int ty = tid / (BN / TN);

    for (int k0 = 0; k0 < Kd; k0 += BK) {
        // A tile -> As[k][m]  (A row-major, k contiguous)
#pragma unroll
        for (int i = 0; i < (BM * BK) / (THREADS * 4); i++) {
            int idx = (tid + i * THREADS) * 4;
            int r = idx / BK, c = idx % BK;
            int gm = m0 + r;
            float4 v = make_float4(0.f, 0.f, 0.f, 0.f);
            if (gm < M) v = *(const float4*)(A + (long)gm * Kd + k0 + c);
            As[c + 0][r] = v.x;
            As[c + 1][r] = v.y;
            As[c + 2][r] = v.z;
            As[c + 3][r] = v.w;
        }
        // B tile -> Bs[k][n]  (B row-major K x N, n contiguous)
#pragma unroll
        for (int i = 0; i < (BK * BN) / (THREADS * 4); i++) {
            int idx = (tid + i * THREADS) * 4;
            int r = idx / BN, c = idx % BN;
            float4 v = *(const float4*)(B + (long)(k0 + r) * N + n0 + c);
            *(float4*)&Bs[r][c] = v;
        }
        __syncthreads();

#pragma unroll
        for (int k = 0; k < BK; k++) {
            float ar[TM], br[TN];
#pragma unroll
            for (int i = 0; i < TM; i++) ar[i] = As[k][ty * TM + i];
#pragma unroll
            for (int j = 0; j < TN; j++) br[j] = Bs[k][tx * TN + j];
#pragma unroll
            for (int i = 0; i < TM; i++)
#pragma unroll
                for (int j = 0; j < TN; j++) acc[i][j] += ar[i] * br[j];
        }
        __syncthreads();
    }

#pragma unroll
    for (int i = 0; i < TM; i++) {
        int gm = m0 + ty * TM + i;
        if (gm >= M) continue;
#pragma unroll
        for (int j = 0; j < TN; j++) {
            int gn = n0 + tx * TN + j;
            C[(long)gm * N + gn] = acc[i][j];
        }
    }
}

// ---------------------------------------------------------------------------
// Softmax over slot axis K (axis=-2 of scores[b][k][m]), per (b,m) column.
// ---------------------------------------------------------------------------
__global__ void softmax_slots(float* __restrict__ S) {
    int idx = blockIdx.x * blockDim.x + threadIdx.x;
    if (idx >= NB * NM) return;
    int b = idx / NM, m = idx % NM;
    float* base = S + (long)b * NS * NM + m;
    float mx = -INFINITY;
#pragma unroll 4
    for (int k = 0; k < NS; k++) mx = fmaxf(mx, base[(long)k * NM]);
    float sum = 0.f;
#pragma unroll 4
    for (int k = 0; k < NS; k++) sum += expf(base[(long)k * NM] - mx);
    float inv = 1.f / sum;
#pragma unroll 4
    for (int k = 0; k < NS; k++) {
        long o = (long)k * NM;
        base[o] = expf(base[o] - mx) * inv;
    }
}

// ---------------------------------------------------------------------------
// Row renorm: attn[b,k,:] /= (sum_m attn + EPS). One block per (b,k).
// ---------------------------------------------------------------------------
__global__ void attn_rownorm(float* __restrict__ S) {
    int row = blockIdx.x;
    float* x = S + (long)row * NM;
    float s = 0.f;
    for (int i = threadIdx.x; i < NM; i += blockDim.x) s += x[i];
    __shared__ float red[256];
    red[threadIdx.x] = s;
    __syncthreads();
    for (int off = 128; off > 0; off >>= 1) {
        if (threadIdx.x < off) red[threadIdx.x] += red[threadIdx.x + off];
        __syncthreads();
    }
    float inv = 1.f / (red[0] + EPS_F);
    for (int i = threadIdx.x; i < NM; i += blockDim.x) x[i] *= inv;
}

// ---------------------------------------------------------------------------
// GRU pointwise combine: slots <- (1-z)*n + z*slots
// ---------------------------------------------------------------------------
__global__ void gru_combine(const float* __restrict__ gx,
                            const float* __restrict__ gh,
                            float* __restrict__ slots) {
    int idx = blockIdx.x * blockDim.x + threadIdx.x;
    if (idx >= NB * NS * DD) return;
    int r = idx / DD, c = idx % DD;
    long b3 = (long)r * 3 * DD;
    float xr = gx[b3 + c], xz = gx[b3 + DD + c], xn = gx[b3 + 2 * DD + c];
    float hr = gh[b3 + c], hz = gh[b3 + DD + c], hn = gh[b3 + 2 * DD + c];
    float rg = 1.f / (1.f + expf(-(xr + hr)));
    float zg = 1.f / (1.f + expf(-(xz + hz)));
    float ng = tanhf(xn + rg * hn);
    float h = slots[idx];
    slots[idx] = (1.f - zg) * ng + zg * h;
}

// ---------------------------------------------------------------------------
// Launch
// ---------------------------------------------------------------------------
extern "C" void kernel_launch(void* const* d_in, const int* in_sizes, int n_in,
                              void* d_out, int out_size)
{
    const float* slots_in = (const float*)d_in[0];
    const float* P        = (const float*)d_in[1];
    const float* Wq       = (const float*)d_in[2];
    const float* Wk       = (const float*)d_in[3];
    const float* Wv       = (const float*)d_in[4];
    const float* wih      = (const float*)d_in[5];
    const float* whh      = (const float*)d_in[6];
    const float* bih      = (const float*)d_in[7];
    const float* bhh      = (const float*)d_in[8];
    const float* snw      = (const float*)d_in[9];
    const float* inw      = (const float*)d_in[10];

    float *kproj, *vproj, *rsP, *slots, *rss, *q, *scores, *updates, *gx, *gh;
    cudaGetSymbolAddress((void**)&kproj,   g_kproj);
    cudaGetSymbolAddress((void**)&vproj,   g_vproj);
    cudaGetSymbolAddress((void**)&rsP,     g_rsP);
    cudaGetSymbolAddress((void**)&slots,   g_slots);
    cudaGetSymbolAddress((void**)&rss,     g_rss);
    cudaGetSymbolAddress((void**)&q,       g_q);
    cudaGetSymbolAddress((void**)&scores,  g_scores);
    cudaGetSymbolAddress((void**)&updates, g_updates);
    cudaGetSymbolAddress((void**)&gx,      g_gx);
    cudaGetSymbolAddress((void**)&gh,      g_gh);

    cudaMemcpyAsync(slots, slots_in, (size_t)NB * NS * DD * sizeof(float),
                    cudaMemcpyDeviceToDevice, 0);

    // input rmsnorm scales, then K/V projections (rmsnorm folded into A-load)
    rms_rows<<<NB * NM, 256>>>(P, rsP, DD);

    gemm_nt<128, 128, 16, 8, 8><<<dim3(DD / 128, (NB * NM) / 128, 1), 256>>>(
        P, Wk, kproj, NB * NM, DD, DD, 0, 0, 0, rsP, inw, nullptr, 1.f);
    gemm_nt<128, 128, 16, 8, 8><<<dim3(DD / 128, (NB * NM) / 128, 1), 256>>>(
        P, Wv, vproj, NB * NM, DD, DD, 0, 0, 0, rsP, inw, nullptr, 1.f);

    for (int it = 0; it < 3; it++) {
        // slot rmsnorm + q projection
        rms_rows<<<NB * NS, 256>>>(slots, rss, DD);
        gemm_nt<128, 128, 16, 8, 8><<<dim3(DD / 128, (NB * NS) / 128, 1), 256>>>(
            slots, Wq, q, NB * NS, DD, DD, 0, 0, 0, rss, snw, nullptr, 1.f);

        // scores[b,k,m] = SCALE * q[b,k,:] . kproj[b,m,:]
        gemm_nt<128, 128, 16, 8, 8><<<dim3(NM / 128, 1, NB), 256>>>(
            q, kproj, scores, NS, NM, DD,
            (long)NS * DD, (long)NM * DD, (long)NS * NM,
            nullptr, nullptr, nullptr, SCALE_F);

        // softmax over K, then renorm over M
        softmax_slots<<<(NB * NM + 255) / 256, 256>>>(scores);
        attn_rownorm<<<NB * NS, 256>>>(scores);

        // updates[b,k,:] = attn[b,k,:] @ vproj[b]
        gemm_nn<64, 128, 16, 4, 8><<<dim3(DD / 128, 1, NB), 256>>>(
            scores, vproj, updates, NS, DD, NM,
            (long)NS * NM, (long)NM * DD, (long)NS * DD);

        // GRU gates
        gemm_nt<128, 128, 16, 8, 8><<<dim3((3 * DD) / 128, (NB * NS) / 128, 1), 256>>>(
            updates, wih, gx, NB * NS, 3 * DD, DD, 0, 0, 0,
            nullptr, nullptr, bih, 1.f);
        gemm_nt<128, 128, 16, 8, 8><<<dim3((3 * DD) / 128, (NB * NS) / 128, 1), 256>>>(
            slots, whh, gh, NB * NS, 3 * DD, DD, 0, 0, 0,
            nullptr, nullptr, bhh, 1.f);

        gru_combine<<<(NB * NS * DD) / 256, 256>>>(gx, gh, slots);
    }

    cudaMemcpyAsync(d_out, slots, (size_t)NB * NS * DD * sizeof(float),
                    cudaMemcpyDeviceToDevice, 0);
}

// round 3
// speedup vs baseline: 2.7439x; 2.7439x over previous
#include <cuda_runtime.h>
#include <cuda_bf16.h>
#include <math.h>
#include <stdint.h>

#define DD 1024
#define NB 8
#define NS 64
#define NM 4096
#define EPS_F 1e-6f
#define SCALE_F 0.03125f

// ---------------------------------------------------------------------------
// Scratch (static device globals)
// ---------------------------------------------------------------------------
__device__ __nv_bfloat16 g_pnh[(long)NB*NM*DD], g_pnl[(long)NB*NM*DD];   // rmsnormed P hi/lo
__device__ __nv_bfloat16 g_kph[(long)NB*NM*DD], g_kpl[(long)NB*NM*DD];   // kproj [bm][d]
__device__ __nv_bfloat16 g_vth[(long)NB*NM*DD], g_vtl[(long)NB*NM*DD];   // vprojT [d][b*4096+m]
__device__ __nv_bfloat16 g_wqh[DD*DD],    g_wql[DD*DD];
__device__ __nv_bfloat16 g_wkh[DD*DD],    g_wkl[DD*DD];
__device__ __nv_bfloat16 g_wvh[DD*DD],    g_wvl[DD*DD];
__device__ __nv_bfloat16 g_wihh[3*DD*DD], g_wihl[3*DD*DD];
__device__ __nv_bfloat16 g_whhh[3*DD*DD], g_whhl[3*DD*DD];
__device__ float g_rsP[NB*NM];
__device__ float g_slots[NB*NS*DD];
__device__ float g_rss[NB*NS];
__device__ __nv_bfloat16 g_sh[NB*NS*DD],  g_sl[NB*NS*DD];    // raw slots hi/lo
__device__ __nv_bfloat16 g_snh[NB*NS*DD], g_snl[NB*NS*DD];   // normed slots hi/lo
__device__ __nv_bfloat16 g_qh[NB*NS*DD],  g_ql[NB*NS*DD];
__device__ float g_scT[(long)NB*NM*NS];                      // scoresT [b][m][k]
__device__ __nv_bfloat16 g_ath[(long)NB*NS*NM], g_atl[(long)NB*NS*NM];  // attn [b][k][m]
__device__ __nv_bfloat16 g_uh[NB*NS*DD],  g_ul[NB*NS*DD];    // updates hi/lo [bk][d]
__device__ float g_gx[NB*NS*3*DD], g_gh[NB*NS*3*DD];

// ---------------------------------------------------------------------------
// Helpers
// ---------------------------------------------------------------------------
__device__ __forceinline__ uint32_t smem_u32(const void* p) {
    uint32_t a;
    asm("{ .reg .u64 t; cvta.to.shared.u64 t, %1; cvt.u32.u64 %0, t; }" : "=r"(a) : "l"(p));
    return a;
}
__device__ __forceinline__ void cpa16(uint32_t dst, const void* src) {
    asm volatile("cp.async.cg.shared.global [%0], [%1], 16;" :: "r"(dst), "l"(src) : "memory");
}
#define CP_COMMIT() asm volatile("cp.async.commit_group;" ::: "memory")
#define CP_WAIT1()  asm volatile("cp.async.wait_group 1;" ::: "memory")

#define LDSM4(r, addr) \
    asm volatile("ldmatrix.sync.aligned.m8n8.x4.shared.b16 {%0,%1,%2,%3}, [%4];" \
        : "=r"((r)[0]), "=r"((r)[1]), "=r"((r)[2]), "=r"((r)[3]) : "r"(addr))

#define MMA4(d, a, b0, b1) \
    asm volatile("mma.sync.aligned.m16n8k16.row.col.f32.bf16.bf16.f32 " \
        "{%0,%1,%2,%3},{%4,%5,%6,%7},{%8,%9},{%0,%1,%2,%3};" \
        : "+f"((d)[0]), "+f"((d)[1]), "+f"((d)[2]), "+f"((d)[3]) \
        : "r"((a)[0]), "r"((a)[1]), "r"((a)[2]), "r"((a)[3]), "r"(b0), "r"(b1))

__device__ __forceinline__ uint32_t pack2(float a, float b) {
    __nv_bfloat162 t = __floats2bfloat162_rn(a, b);
    return *reinterpret_cast<uint32_t*>(&t);
}
__device__ __forceinline__ void d2(float v, float& hi, float& lo) {
    __nv_bfloat16 h = __float2bfloat16_rn(v);
    hi = __bfloat162float(h);
    lo = v - hi;
}

// ---------------------------------------------------------------------------
// Prefetch one BK=32 chunk of A(128 rows) + B(TN rows), hi & lo, into a stage.
// SMEM row stride = 40 bf16 = 80 B (16B-aligned, conflict-free for ldmatrix).
// ---------------------------------------------------------------------------
template <int TN>
__device__ __forceinline__ void prefetch_tiles(
    uint32_t stage,
    const __nv_bfloat16* __restrict__ Ah, const __nv_bfloat16* __restrict__ Al,
    const __nv_bfloat16* __restrict__ Bh, const __nv_bfloat16* __restrict__ Bl,
    long lda, long ldb, int m0, int n0, int k0, int tid)
{
    constexpr int AL_OFF = 128 * 80;       // 10240
    constexpr int BH_OFF = 2 * 128 * 80;   // 20480
#pragma unroll
    for (int i = 0; i < 2; i++) {
        int idx = tid + i * 256;
        int r = idx >> 2, ch = idx & 3;
        long g = (long)(m0 + r) * lda + k0 + ch * 8;
        uint32_t d = stage + (uint32_t)(r * 80 + ch * 16);
        cpa16(d, Ah + g);
        cpa16(d + AL_OFF, Al + g);
    }
#pragma unroll
    for (int i = 0; i < TN / 64; i++) {
        int idx = tid + i * 256;
        int r = idx >> 2, ch = idx & 3;
        long g = (long)(n0 + r) * ldb + k0 + ch * 8;
        uint32_t d = stage + BH_OFF + (uint32_t)(r * 80 + ch * 16);
        cpa16(d, Bh + g);
        cpa16(d + TN * 80, Bl + g);
    }
}

// ---------------------------------------------------------------------------
// bf16x3 NT GEMM via mma.sync:  D[m][n] = sum_k (Ahi+Alo)[m][k]*(Bhi+Blo)[n][k]
// (drops lo*lo). BM=128, TN in {64,128}, BK=32, 8 warps (4M x 2N), dbl-buffer.
// EPI: 0 = fp32 out (alpha, bias) C[m][n]
//      1 = bf16 hi/lo out         C[m][n]
//      2 = bf16 hi/lo TRANSPOSED  Ct[n][m] (SMEM-staged, coalesced)
// M % 128 == 0, N % TN == 0, K % 32 == 0 required (true for all calls).
// ---------------------------------------------------------------------------
template <int TN, int EPI>
__global__ __launch_bounds__(256, 1)
void mma_nt(const __nv_bfloat16* __restrict__ Ah, const __nv_bfloat16* __restrict__ Al,
            long lda, long sA,
            const __nv_bfloat16* __restrict__ Bh, const __nv_bfloat16* __restrict__ Bl,
            long ldb, long sB,
            float* __restrict__ Cf,
            __nv_bfloat16* __restrict__ Ch, __nv_bfloat16* __restrict__ Cl,
            long ldc, long sC,
            int Kd, const float* __restrict__ bias, float alpha)
{
    constexpr int WN = TN / 2;
    constexpr int NF = WN / 8;
    constexpr int NF16 = WN / 16;
    constexpr int AL_OFF = 10240;
    constexpr int BH_OFF = 20480;
    constexpr int STAGE = 20480 + TN * 160;

    extern __shared__ char smem[];
    const uint32_t sb = smem_u32(smem);
    const int tid = threadIdx.x, lane = tid & 31, wid = tid >> 5;
    const int wm = wid & 3, wn = wid >> 2;

    const int m0 = blockIdx.y * 128, n0 = blockIdx.x * TN;
    Ah += (long)blockIdx.z * sA;  Al += (long)blockIdx.z * sA;
    Bh += (long)blockIdx.z * sB;  Bl += (long)blockIdx.z * sB;

    float acc[2][NF][4];
#pragma unroll
    for (int i = 0; i < 2; i++)
#pragma unroll
        for (int j = 0; j < NF; j++)
#pragma unroll
            for (int k = 0; k < 4; k++) acc[i][j][k] = 0.f;

    // per-thread ldmatrix offsets within a stage
    const uint32_t aoff = (uint32_t)((wm * 32 + (lane & 15)) * 80 + (lane >> 4) * 16);
    const uint32_t boff = (uint32_t)(BH_OFF + (wn * WN + (lane & 15)) * 80 + (lane >> 4) * 16);

    const int NC = Kd >> 5;
    prefetch_tiles<TN>(sb,         Ah, Al, Bh, Bl, lda, ldb, m0, n0, 0,  tid);
    CP_COMMIT();
    prefetch_tiles<TN>(sb + STAGE, Ah, Al, Bh, Bl, lda, ldb, m0, n0, 32, tid);
    CP_COMMIT();

    for (int c = 0; c < NC; c++) {
        CP_WAIT1();
        __syncthreads();
        const uint32_t st = sb + (c & 1) * STAGE;
#pragma unroll
        for (int ks = 0; ks < 2; ks++) {
            const uint32_t ka = st + aoff + ks * 32;
            const uint32_t kb = st + boff + ks * 32;
            uint32_t ah[2][4], al[2][4];
            LDSM4(ah[0], ka);
            LDSM4(ah[1], ka + 16 * 80);
            LDSM4(al[0], ka + AL_OFF);
            LDSM4(al[1], ka + AL_OFF + 16 * 80);
            uint32_t bh[NF16][4], bl[NF16][4];
#pragma unroll
            for (int nf = 0; nf < NF16; nf++) {
                LDSM4(bh[nf], kb + nf * 16 * 80);
                LDSM4(bl[nf], kb + TN * 80 + nf * 16 * 80);
            }
#pragma unroll
            for (int mf = 0; mf < 2; mf++)
#pragma unroll
                for (int nf = 0; nf < NF16; nf++) {
                    MMA4(acc[mf][2*nf],   ah[mf], bh[nf][0], bh[nf][2]);
                    MMA4(acc[mf][2*nf+1], ah[mf], bh[nf][1], bh[nf][3]);
                    MMA4(acc[mf][2*nf],   ah[mf], bl[nf][0], bl[nf][2]);
                    MMA4(acc[mf][2*nf+1], ah[mf], bl[nf][1], bl[nf][3]);
                    MMA4(acc[mf][2*nf],   al[mf], bh[nf][0], bh[nf][2]);
                    MMA4(acc[mf][2*nf+1], al[mf], bh[nf][1], bh[nf][3]);
                }
        }
        __syncthreads();
        if (c + 2 < NC)
            prefetch_tiles<TN>(sb + (c & 1) * STAGE, Ah, Al, Bh, Bl,
                               lda, ldb, m0, n0, (c + 2) * 32, tid);
        CP_COMMIT();
    }

    // ---- epilogue ----
    const int rbase = m0 + wm * 32;
    const int cbase = n0 + wn * WN;
    if (EPI == 0) {
        float* C = Cf + (long)blockIdx.z * sC;
#pragma unroll
        for (int mf = 0; mf < 2; mf++) {
            int row = rbase + mf * 16 + (lane >> 2);
#pragma unroll
            for (int nf = 0; nf < NF; nf++) {
                int col = cbase + nf * 8 + (lane & 3) * 2;
                float b0 = bias ? bias[col] : 0.f, b1 = bias ? bias[col + 1] : 0.f;
                float2 v0 = make_float2(acc[mf][nf][0] * alpha + b0,
                                        acc[mf][nf][1] * alpha + b1);
                float2 v1 = make_float2(acc[mf][nf][2] * alpha + b0,
                                        acc[mf][nf][3] * alpha + b1);
                *(float2*)(C + (long)row * ldc + col) = v0;
                *(float2*)(C + (long)(row + 8) * ldc + col) = v1;
            }
        }
    } else if (EPI == 1) {
        __nv_bfloat16* CH = Ch + (long)blockIdx.z * sC;
        __nv_bfloat16* CL = Cl + (long)blockIdx.z * sC;
#pragma unroll
        for (int mf = 0; mf < 2; mf++) {
            int row = rbase + mf * 16 + (lane >> 2);
#pragma unroll
            for (int nf = 0; nf < NF; nf++) {
                int col = cbase + nf * 8 + (lane & 3) * 2;
                float h0, l0, h1, l1;
                d2(acc[mf][nf][0] * alpha, h0, l0);
                d2(acc[mf][nf][1] * alpha, h1, l1);
                *(uint32_t*)(CH + (long)row * ldc + col) = pack2(h0, h1);
                *(uint32_t*)(CL + (long)row * ldc + col) = pack2(l0, l1);
                d2(acc[mf][nf][2] * alpha, h0, l0);
                d2(acc[mf][nf][3] * alpha, h1, l1);
                *(uint32_t*)(CH + (long)(row + 8) * ldc + col) = pack2(h0, h1);
                *(uint32_t*)(CL + (long)(row + 8) * ldc + col) = pack2(l0, l1);
            }
        }
    } else {
        // stage fp32 transpose through smem, then coalesced hi/lo writes
        float* ts = reinterpret_cast<float*>(smem);
        const int rl = wm * 32;
        const int cl = wn * WN;
#pragma unroll
        for (int mf = 0; mf < 2; mf++) {
            int row = rl + mf * 16 + (lane >> 2);
#pragma unroll
            for (int nf = 0; nf < NF; nf++) {
                int col = cl + nf * 8 + (lane & 3) * 2;
                ts[(col + 0) * 132 + row]     = acc[mf][nf][0] * alpha;
                ts[(col + 1) * 132 + row]     = acc[mf][nf][1] * alpha;
                ts[(col + 0) * 132 + row + 8] = acc[mf][nf][2] * alpha;
                ts[(col + 1) * 132 + row + 8] = acc[mf][nf][3] * alpha;
            }
        }
        __syncthreads();
        __nv_bfloat16* CH = Ch + (long)blockIdx.z * sC;
        __nv_bfloat16* CL = Cl + (long)blockIdx.z * sC;
#pragma unroll
        for (int rep = 0; rep < TN / 8; rep++) {
            int n = rep * 8 + wid;
            float v0 = ts[n * 132 + lane * 4 + 0];
            float v1 = ts[n * 132 + lane * 4 + 1];
            float v2 = ts[n * 132 + lane * 4 + 2];
            float v3 = ts[n * 132 + lane * 4 + 3];
            float h0, l0, h1, l1, h2, l2, h3, l3;
            d2(v0, h0, l0); d2(v1, h1, l1); d2(v2, h2, l2); d2(v3, h3, l3);
            long o = (long)(n0 + n) * ldc + m0 + lane * 4;
            *(uint2*)(CH + o) = make_uint2(pack2(h0, h1), pack2(h2, h3));
            *(uint2*)(CL + o) = make_uint2(pack2(l0, l1), pack2(l2, l3));
        }
    }
}

// ---------------------------------------------------------------------------
// Elementwise kernels
// ---------------------------------------------------------------------------
__global__ void rms_rows(const float* __restrict__ X, float* __restrict__ rs) {
    int r = blockIdx.x;
    float4 v = ((const float4*)(X + (long)r * DD))[threadIdx.x];
    float s = v.x * v.x + v.y * v.y + v.z * v.z + v.w * v.w;
    for (int o = 16; o; o >>= 1) s += __shfl_xor_sync(0xffffffffu, s, o);
    __shared__ float red[8];
    if ((threadIdx.x & 31) == 0) red[threadIdx.x >> 5] = s;
    __syncthreads();
    if (threadIdx.x == 0) {
        float t = 0.f;
#pragma unroll
        for (int i = 0; i < 8; i++) t += red[i];
        rs[r] = rsqrtf(t * (1.f / DD) + EPS_F);
    }
}

__global__ void decomp4(const float* __restrict__ X,
                        __nv_bfloat16* __restrict__ H, __nv_bfloat16* __restrict__ L,
                        long n4, const float* __restrict__ rsc,
                        const float* __restrict__ csc, int d4) {
    long i = (long)blockIdx.x * blockDim.x + threadIdx.x;
    if (i >= n4) return;
    float4 v = ((const float4*)X)[i];
    if (rsc) {
        float s = rsc[i / d4];
        v.x *= s; v.y *= s; v.z *= s; v.w *= s;
    }
    if (csc) {
        int c = (int)(i % d4) * 4;
        v.x *= csc[c]; v.y *= csc[c + 1]; v.z *= csc[c + 2]; v.w *= csc[c + 3];
    }
    float h0, h1, h2, h3, l0, l1, l2, l3;
    d2(v.x, h0, l0); d2(v.y, h1, l1); d2(v.z, h2, l2); d2(v.w, h3, l3);
    ((uint2*)H)[i] = make_uint2(pack2(h0, h1), pack2(h2, h3));
    ((uint2*)L)[i] = make_uint2(pack2(l0, l1), pack2(l2, l3));
}

__global__ void softmax64(float* __restrict__ S) {
    long idx = (long)blockIdx.x * blockDim.x + threadIdx.x;
    if (idx >= (long)NB * NM) return;
    float4* p = (float4*)(S + idx * NS);
    float4 v[16];
    float mx = -INFINITY;
#pragma unroll
    for (int i = 0; i < 16; i++) {
        v[i] = p[i];
        mx = fmaxf(mx, fmaxf(fmaxf(v[i].x, v[i].y), fmaxf(v[i].z, v[i].w)));
    }
    float sum = 0.f;
#pragma unroll
    for (int i = 0; i < 16; i++) {
        v[i].x = __expf(v[i].x - mx); v[i].y = __expf(v[i].y - mx);
        v[i].z = __expf(v[i].z - mx); v[i].w = __expf(v[i].w - mx);
        sum += v[i].x + v[i].y + v[i].z + v[i].w;
    }
    float inv = 1.f / sum;
#pragma unroll
    for (int i = 0; i < 16; i++) {
        v[i].x *= inv; v[i].y *= inv; v[i].z *= inv; v[i].w *= inv;
        p[i] = v[i];
    }
}

__global__ void renorm_tr(const float* __restrict__ S,
                          __nv_bfloat16* __restrict__ AH, __nv_bfloat16* __restrict__ AL) {
    int b = blockIdx.x >> 6, k = blockIdx.x & 63;
    const float* p = S + (long)b * NM * NS + k;
    float s = 0.f;
    for (int m = threadIdx.x; m < NM; m += 256) s += p[(long)m * NS];
    for (int o = 16; o; o >>= 1) s += __shfl_xor_sync(0xffffffffu, s, o);
    __shared__ float red[8];
    __shared__ float sinv;
    if ((threadIdx.x & 31) == 0) red[threadIdx.x >> 5] = s;
    __syncthreads();
    if (threadIdx.x == 0) {
        float t = 0.f;
#pragma unroll
        for (int i = 0; i < 8; i++) t += red[i];
        sinv = 1.f / (t + EPS_F);
    }
    __syncthreads();
    float inv = sinv;
    long ob = ((long)b * NS + k) * NM;
    for (int m = threadIdx.x; m < NM; m += 256) {
        float v = p[(long)m * NS] * inv;
        float h, l;
        d2(v, h, l);
        AH[ob + m] = __float2bfloat16_rn(h);
        AL[ob + m] = __float2bfloat16_rn(l);
    }
}

__global__ void gru_combine(const float* __restrict__ gx, const float* __restrict__ gh,
                            float* __restrict__ slots,
                            __nv_bfloat16* __restrict__ SH, __nv_bfloat16* __restrict__ SL) {
    long i = (long)blockIdx.x * blockDim.x + threadIdx.x;
    if (i >= (long)NB * NS * DD) return;
    int r = (int)(i >> 10), c = (int)(i & 1023);
    long b3 = (long)r * 3 * DD + c;
    float xr = gx[b3], xz = gx[b3 + DD], xn = gx[b3 + 2 * DD];
    float hr = gh[b3], hz = gh[b3 + DD], hn = gh[b3 + 2 * DD];
    float rg = 1.f / (1.f + __expf(-(xr + hr)));
    float zg = 1.f / (1.f + __expf(-(xz + hz)));
    float ng = tanhf(xn + rg * hn);
    float o = (1.f - zg) * ng + zg * slots[i];
    slots[i] = o;
    float h, l;
    d2(o, h, l);
    SH[i] = __float2bfloat16_rn(h);
    SL[i] = __float2bfloat16_rn(l);
}

// ---------------------------------------------------------------------------
// Launch
// ---------------------------------------------------------------------------
extern "C" void kernel_launch(void* const* d_in, const int* in_sizes, int n_in,
                              void* d_out, int out_size)
{
    const float* slots_in = (const float*)d_in[0];
    const float* P        = (const float*)d_in[1];
    const float* Wq       = (const float*)d_in[2];
    const float* Wk       = (const float*)d_in[3];
    const float* Wv       = (const float*)d_in[4];
    const float* wih      = (const float*)d_in[5];
    const float* whh      = (const float*)d_in[6];
    const float* bih      = (const float*)d_in[7];
    const float* bhh      = (const float*)d_in[8];
    const float* snw      = (const float*)d_in[9];
    const float* inw      = (const float*)d_in[10];

    __nv_bfloat16 *pnh, *pnl, *kph, *kpl, *vth, *vtl;
    __nv_bfloat16 *wqh, *wql, *wkh, *wkl, *wvh, *wvl, *wihh, *wihl, *whhh, *whhl;
    __nv_bfloat16 *sh, *sl, *snh, *snl, *qh, *ql, *ath, *atl, *uh, *ul;
    float *rsP, *slots, *rss, *scT, *gx, *gh;
    cudaGetSymbolAddress((void**)&pnh, g_pnh);   cudaGetSymbolAddress((void**)&pnl, g_pnl);
    cudaGetSymbolAddress((void**)&kph, g_kph);   cudaGetSymbolAddress((void**)&kpl, g_kpl);
    cudaGetSymbolAddress((void**)&vth, g_vth);   cudaGetSymbolAddress((void**)&vtl, g_vtl);
    cudaGetSymbolAddress((void**)&wqh, g_wqh);   cudaGetSymbolAddress((void**)&wql, g_wql);
    cudaGetSymbolAddress((void**)&wkh, g_wkh);   cudaGetSymbolAddress((void**)&wkl, g_wkl);
    cudaGetSymbolAddress((void**)&wvh, g_wvh);   cudaGetSymbolAddress((void**)&wvl, g_wvl);
    cudaGetSymbolAddress((void**)&wihh, g_wihh); cudaGetSymbolAddress((void**)&wihl, g_wihl);
    cudaGetSymbolAddress((void**)&whhh, g_whhh); cudaGetSymbolAddress((void**)&whhl, g_whhl);
    cudaGetSymbolAddress((void**)&sh, g_sh);     cudaGetSymbolAddress((void**)&sl, g_sl);
    cudaGetSymbolAddress((void**)&snh, g_snh);   cudaGetSymbolAddress((void**)&snl, g_snl);
    cudaGetSymbolAddress((void**)&qh, g_qh);     cudaGetSymbolAddress((void**)&ql, g_ql);
    cudaGetSymbolAddress((void**)&ath, g_ath);   cudaGetSymbolAddress((void**)&atl, g_atl);
    cudaGetSymbolAddress((void**)&uh, g_uh);     cudaGetSymbolAddress((void**)&ul, g_ul);
    cudaGetSymbolAddress((void**)&rsP, g_rsP);   cudaGetSymbolAddress((void**)&slots, g_slots);
    cudaGetSymbolAddress((void**)&rss, g_rss);   cudaGetSymbolAddress((void**)&scT, g_scT);
    cudaGetSymbolAddress((void**)&gx, g_gx);     cudaGetSymbolAddress((void**)&gh, g_gh);

    constexpr int SMEM128 = 2 * (20480 + 128 * 160);  // 81920
    constexpr int SMEM64  = 2 * (20480 + 64 * 160);   // 61440
    cudaFuncSetAttribute(mma_nt<128, 0>, cudaFuncAttributeMaxDynamicSharedMemorySize, SMEM128);
    cudaFuncSetAttribute(mma_nt<128, 1>, cudaFuncAttributeMaxDynamicSharedMemorySize, SMEM128);
    cudaFuncSetAttribute(mma_nt<128, 2>, cudaFuncAttributeMaxDynamicSharedMemorySize, SMEM128);
    cudaFuncSetAttribute(mma_nt<64, 0>,  cudaFuncAttributeMaxDynamicSharedMemorySize, SMEM64);
    cudaFuncSetAttribute(mma_nt<64, 2>,  cudaFuncAttributeMaxDynamicSharedMemorySize, SMEM64);

    // ---- weights + initial slots decomposition ----
    decomp4<<<DD * DD / 4 / 256, 256>>>(Wq, wqh, wql, DD * DD / 4, nullptr, nullptr, DD / 4);
    decomp4<<<DD * DD / 4 / 256, 256>>>(Wk, wkh, wkl, DD * DD / 4, nullptr, nullptr, DD / 4);
    decomp4<<<DD * DD / 4 / 256, 256>>>(Wv, wvh, wvl, DD * DD / 4, nullptr, nullptr, DD / 4);
    decomp4<<<3 * DD * DD / 4 / 256, 256>>>(wih, wihh, wihl, 3 * DD * DD / 4, nullptr, nullptr, DD / 4);
    decomp4<<<3 * DD * DD / 4 / 256, 256>>>(whh, whhh, whhl, 3 * DD * DD / 4, nullptr, nullptr, DD / 4);

    cudaMemcpyAsync(slots, slots_in, (size_t)NB * NS * DD * sizeof(float),
                    cudaMemcpyDeviceToDevice, 0);
    decomp4<<<NB * NS * DD / 4 / 256, 256>>>(slots, sh, sl, NB * NS * DD / 4,
                                             nullptr, nullptr, DD / 4);

    // ---- Pn = rmsnorm(P)*w (fused into decomposition) ----
    rms_rows<<<NB * NM, 256>>>(P, rsP);
    decomp4<<<(int)((long)NB * NM * DD / 4 / 256), 256>>>(
        P, pnh, pnl, (long)NB * NM * DD / 4, rsP, inw, DD / 4);

    // ---- K/V projections ----
    mma_nt<128, 1><<<dim3(DD / 128, NB * NM / 128, 1), 256, SMEM128>>>(
        pnh, pnl, DD, 0, wkh, wkl, DD, 0,
        nullptr, kph, kpl, DD, 0, DD, nullptr, 1.f);
    mma_nt<128, 2><<<dim3(DD / 128, NB * NM / 128, 1), 256, SMEM128>>>(
        pnh, pnl, DD, 0, wvh, wvl, DD, 0,
        nullptr, vth, vtl, (long)NB * NM, 0, DD, nullptr, 1.f);

    for (int it = 0; it < 3; it++) {
        rms_rows<<<NB * NS, 256>>>(slots, rss);
        decomp4<<<NB * NS * DD / 4 / 256, 256>>>(slots, snh, snl, NB * NS * DD / 4,
                                                 rss, snw, DD / 4);
        // q = sn @ Wq^T
        mma_nt<128, 1><<<dim3(DD / 128, NB * NS / 128, 1), 256, SMEM128>>>(
            snh, snl, DD, 0, wqh, wql, DD, 0,
            nullptr, qh, ql, DD, 0, DD, nullptr, 1.f);

        // scoresT[b][m][k] = SCALE * kproj[b] @ q[b]^T
        mma_nt<64, 0><<<dim3(1, NM / 128, NB), 256, SMEM64>>>(
            kph, kpl, DD, (long)NM * DD, qh, ql, DD, (long)NS * DD,
            scT, nullptr, nullptr, NS, (long)NM * NS, DD, nullptr, SCALE_F);

        softmax64<<<NB * NM / 256, 256>>>(scT);
        renorm_tr<<<NB * NS, 256>>>(scT, ath, atl);

        // updates[b][k][d] = (vprojT[b] @ attn[b]^T)^T
        mma_nt<64, 2><<<dim3(1, DD / 128, NB), 256, SMEM64>>>(
            vth, vtl, (long)NB * NM, NM, ath, atl, NM, (long)NS * NM,
            nullptr, uh, ul, DD, (long)NS * DD, NM, nullptr, 1.f);

        // GRU gate pre-activations
        mma_nt<128, 0><<<dim3(3 * DD / 128, NB * NS / 128, 1), 256, SMEM128>>>(
            uh, ul, DD, 0, wihh, wihl, DD, 0,
            gx, nullptr, nullptr, 3 * DD, 0, DD, bih, 1.f);
        mma_nt<128, 0><<<dim3(3 * DD / 128, NB * NS / 128, 1), 256, SMEM128>>>(
            sh, sl, DD, 0, whhh, whhl, DD, 0,
            gh, nullptr, nullptr, 3 * DD, 0, DD, bhh, 1.f);

        gru_combine<<<NB * NS * DD / 256, 256>>>(gx, gh, slots, sh, sl);
    }

    cudaMemcpyAsync(d_out, slots, (size_t)NB * NS * DD * sizeof(float),
                    cudaMemcpyDeviceToDevice, 0);
}

// round 4
// speedup vs baseline: 3.3921x; 1.2362x over previous
#include <cuda_runtime.h>
#include <cuda_bf16.h>
#include <math.h>
#include <stdint.h>

#define DD 1024
#define NB 8
#define NS 64
#define NM 4096
#define EPS_F 1e-6f
#define SCALE_F 0.03125f

// ---------------------------------------------------------------------------
// Scratch (static device globals)
// ---------------------------------------------------------------------------
__device__ __nv_bfloat16 g_pnh[(long)NB*NM*DD], g_pnl[(long)NB*NM*DD];   // rmsnormed P hi/lo
__device__ __nv_bfloat16 g_kph[(long)NB*NM*DD], g_kpl[(long)NB*NM*DD];   // kproj [bm][d]
__device__ __nv_bfloat16 g_vth[(long)NB*NM*DD], g_vtl[(long)NB*NM*DD];   // vprojT [d][b*4096+m]
__device__ __nv_bfloat16 g_wqh[DD*DD],    g_wql[DD*DD];
__device__ __nv_bfloat16 g_wkh[DD*DD],    g_wkl[DD*DD];
__device__ __nv_bfloat16 g_wvh[DD*DD],    g_wvl[DD*DD];
// packed GRU weights: [0]=wih, [1]=whh
__device__ __nv_bfloat16 g_wch[2L*3*DD*DD], g_wcl[2L*3*DD*DD];
// packed GRU A operands: [0]=updates(u), [1]=slots(s)
__device__ __nv_bfloat16 g_ush[2L*NB*NS*DD], g_usl[2L*NB*NS*DD];
// packed GRU outputs: [0]=gx, [1]=gh
__device__ float g_gcat[2L*NB*NS*3*DD];
__device__ float g_bias2[2*3*DD];
__device__ float g_slots[NB*NS*DD];
__device__ __nv_bfloat16 g_snh[NB*NS*DD], g_snl[NB*NS*DD];   // normed slots hi/lo
__device__ __nv_bfloat16 g_qh[NB*NS*DD],  g_ql[NB*NS*DD];
__device__ float g_scT[(long)NB*NM*NS];                      // scoresT [b][m][k]
__device__ __nv_bfloat16 g_ath[(long)NB*NS*NM], g_atl[(long)NB*NS*NM];  // attn [b][k][m]

#define U_OFF  ((long)NB*NS*DD)        // 524288  (sh/sl live at g_ush+U_OFF)
#define W_OFF  (3L*DD*DD)              // 3145728
#define G_OFF  ((long)NB*NS*3*DD)      // 1572864

// ---------------------------------------------------------------------------
// Helpers
// ---------------------------------------------------------------------------
__device__ __forceinline__ uint32_t smem_u32(const void* p) {
    uint32_t a;
    asm("{ .reg .u64 t; cvta.to.shared.u64 t, %1; cvt.u32.u64 %0, t; }" : "=r"(a) : "l"(p));
    return a;
}
__device__ __forceinline__ void cpa16(uint32_t dst, const void* src) {
    asm volatile("cp.async.cg.shared.global [%0], [%1], 16;" :: "r"(dst), "l"(src) : "memory");
}
#define CP_COMMIT() asm volatile("cp.async.commit_group;" ::: "memory")
#define CP_WAIT1()  asm volatile("cp.async.wait_group 1;" ::: "memory")

#define LDSM4(r, addr) \
    asm volatile("ldmatrix.sync.aligned.m8n8.x4.shared.b16 {%0,%1,%2,%3}, [%4];" \
        : "=r"((r)[0]), "=r"((r)[1]), "=r"((r)[2]), "=r"((r)[3]) : "r"(addr))

#define MMA4(d, a, b0, b1) \
    asm volatile("mma.sync.aligned.m16n8k16.row.col.f32.bf16.bf16.f32 " \
        "{%0,%1,%2,%3},{%4,%5,%6,%7},{%8,%9},{%0,%1,%2,%3};" \
        : "+f"((d)[0]), "+f"((d)[1]), "+f"((d)[2]), "+f"((d)[3]) \
        : "r"((a)[0]), "r"((a)[1]), "r"((a)[2]), "r"((a)[3]), "r"(b0), "r"(b1))

__device__ __forceinline__ uint32_t pack2(float a, float b) {
    __nv_bfloat162 t = __floats2bfloat162_rn(a, b);
    return *reinterpret_cast<uint32_t*>(&t);
}
__device__ __forceinline__ void d2(float v, float& hi, float& lo) {
    __nv_bfloat16 h = __float2bfloat16_rn(v);
    hi = __bfloat162float(h);
    lo = v - hi;
}

// ---------------------------------------------------------------------------
// Prefetch one BK=32 chunk of A(BM rows) + B(TN rows), hi & lo, into a stage.
// SMEM row stride = 80 B (16B-aligned, conflict-free ldmatrix).
// ---------------------------------------------------------------------------
template <int BM, int TN>
__device__ __forceinline__ void prefetch_tiles(
    uint32_t stage,
    const __nv_bfloat16* __restrict__ Ah, const __nv_bfloat16* __restrict__ Al,
    const __nv_bfloat16* __restrict__ Bh, const __nv_bfloat16* __restrict__ Bl,
    long lda, long ldb, int m0, int n0, int k0, int tid)
{
    constexpr int AL_OFF = BM * 80;
    constexpr int BH_OFF = 2 * BM * 80;
#pragma unroll
    for (int i = 0; i < BM / 64; i++) {
        int idx = tid + i * 256;
        int r = idx >> 2, ch = idx & 3;
        long g = (long)(m0 + r) * lda + k0 + ch * 8;
        uint32_t d = stage + (uint32_t)(r * 80 + ch * 16);
        cpa16(d, Ah + g);
        cpa16(d + AL_OFF, Al + g);
    }
#pragma unroll
    for (int i = 0; i < TN / 64; i++) {
        int idx = tid + i * 256;
        int r = idx >> 2, ch = idx & 3;
        long g = (long)(n0 + r) * ldb + k0 + ch * 8;
        uint32_t d = stage + BH_OFF + (uint32_t)(r * 80 + ch * 16);
        cpa16(d, Bh + g);
        cpa16(d + TN * 80, Bl + g);
    }
}

// ---------------------------------------------------------------------------
// bf16x3 NT GEMM via mma.sync:  D[m][n] = sum_k (Ahi+Alo)[m][k]*(Bhi+Blo)[n][k]
// BM in {64,128}, TN in {64,128}, BK=32, 8 warps, dbl-buffered cp.async.
// EPI: 0 = fp32 out (alpha, bias) C[m][n]
//      1 = bf16 hi/lo out         C[m][n]
//      2 = bf16 hi/lo TRANSPOSED  Ct[n][m] (SMEM-staged, coalesced)
// ---------------------------------------------------------------------------
template <int BM, int TN, int EPI>
__global__ __launch_bounds__(256, 2)
void mma_nt(const __nv_bfloat16* __restrict__ Ah, const __nv_bfloat16* __restrict__ Al,
            long lda, long sA,
            const __nv_bfloat16* __restrict__ Bh, const __nv_bfloat16* __restrict__ Bl,
            long ldb, long sB,
            float* __restrict__ Cf,
            __nv_bfloat16* __restrict__ Ch, __nv_bfloat16* __restrict__ Cl,
            long ldc, long sC,
            int Kd, const float* __restrict__ bias, long sBias, float alpha)
{
    constexpr int WMW = BM / 32;       // warps along M
    constexpr int WNW = 8 / WMW;       // warps along N
    constexpr int WN = TN / WNW;       // warp N extent
    constexpr int NF = WN / 8;
    constexpr int NF16 = WN / 16;
    constexpr int AL_OFF = BM * 80;
    constexpr int BH_OFF = 2 * BM * 80;
    constexpr int STAGE = (BM + TN) * 160;

    extern __shared__ char smem[];
    const uint32_t sb = smem_u32(smem);
    const int tid = threadIdx.x, lane = tid & 31, wid = tid >> 5;
    const int wm = wid % WMW, wn = wid / WMW;

    const int m0 = blockIdx.y * BM, n0 = blockIdx.x * TN;
    Ah += (long)blockIdx.z * sA;  Al += (long)blockIdx.z * sA;
    Bh += (long)blockIdx.z * sB;  Bl += (long)blockIdx.z * sB;
    if (bias) bias += (long)blockIdx.z * sBias;

    float acc[2][NF][4];
#pragma unroll
    for (int i = 0; i < 2; i++)
#pragma unroll
        for (int j = 0; j < NF; j++)
#pragma unroll
            for (int k = 0; k < 4; k++) acc[i][j][k] = 0.f;

    const uint32_t aoff = (uint32_t)((wm * 32 + (lane & 15)) * 80 + (lane >> 4) * 16);
    const uint32_t boff = (uint32_t)(BH_OFF + (wn * WN + (lane & 15)) * 80 + (lane >> 4) * 16);

    const int NC = Kd >> 5;
    prefetch_tiles<BM, TN>(sb,         Ah, Al, Bh, Bl, lda, ldb, m0, n0, 0,  tid);
    CP_COMMIT();
    prefetch_tiles<BM, TN>(sb + STAGE, Ah, Al, Bh, Bl, lda, ldb, m0, n0, 32, tid);
    CP_COMMIT();

    for (int c = 0; c < NC; c++) {
        CP_WAIT1();
        __syncthreads();
        const uint32_t st = sb + (c & 1) * STAGE;
#pragma unroll
        for (int ks = 0; ks < 2; ks++) {
            const uint32_t ka = st + aoff + ks * 32;
            const uint32_t kb = st + boff + ks * 32;
            uint32_t ah[2][4], al[2][4];
            LDSM4(ah[0], ka);
            LDSM4(ah[1], ka + 16 * 80);
            LDSM4(al[0], ka + AL_OFF);
            LDSM4(al[1], ka + AL_OFF + 16 * 80);
            uint32_t bh[NF16][4], bl[NF16][4];
#pragma unroll
            for (int nf = 0; nf < NF16; nf++) {
                LDSM4(bh[nf], kb + nf * 16 * 80);
                LDSM4(bl[nf], kb + TN * 80 + nf * 16 * 80);
            }
#pragma unroll
            for (int mf = 0; mf < 2; mf++)
#pragma unroll
                for (int nf = 0; nf < NF16; nf++) {
                    MMA4(acc[mf][2*nf],   ah[mf], bh[nf][0], bh[nf][2]);
                    MMA4(acc[mf][2*nf+1], ah[mf], bh[nf][1], bh[nf][3]);
                    MMA4(acc[mf][2*nf],   ah[mf], bl[nf][0], bl[nf][2]);
                    MMA4(acc[mf][2*nf+1], ah[mf], bl[nf][1], bl[nf][3]);
                    MMA4(acc[mf][2*nf],   al[mf], bh[nf][0], bh[nf][2]);
                    MMA4(acc[mf][2*nf+1], al[mf], bh[nf][1], bh[nf][3]);
                }
        }
        __syncthreads();
        if (c + 2 < NC)
            prefetch_tiles<BM, TN>(sb + (c & 1) * STAGE, Ah, Al, Bh, Bl,
                                   lda, ldb, m0, n0, (c + 2) * 32, tid);
        CP_COMMIT();
    }

    // ---- epilogue ----
    const int rbase = m0 + wm * 32;
    const int cbase = n0 + wn * WN;
    if (EPI == 0) {
        float* C = Cf + (long)blockIdx.z * sC;
#pragma unroll
        for (int mf = 0; mf < 2; mf++) {
            int row = rbase + mf * 16 + (lane >> 2);
#pragma unroll
            for (int nf = 0; nf < NF; nf++) {
                int col = cbase + nf * 8 + (lane & 3) * 2;
                float b0 = bias ? bias[col] : 0.f, b1 = bias ? bias[col + 1] : 0.f;
                float2 v0 = make_float2(acc[mf][nf][0] * alpha + b0,
                                        acc[mf][nf][1] * alpha + b1);
                float2 v1 = make_float2(acc[mf][nf][2] * alpha + b0,
                                        acc[mf][nf][3] * alpha + b1);
                *(float2*)(C + (long)row * ldc + col) = v0;
                *(float2*)(C + (long)(row + 8) * ldc + col) = v1;
            }
        }
    } else if (EPI == 1) {
        __nv_bfloat16* CH = Ch + (long)blockIdx.z * sC;
        __nv_bfloat16* CL = Cl + (long)blockIdx.z * sC;
#pragma unroll
        for (int mf = 0; mf < 2; mf++) {
            int row = rbase + mf * 16 + (lane >> 2);
#pragma unroll
            for (int nf = 0; nf < NF; nf++) {
                int col = cbase + nf * 8 + (lane & 3) * 2;
                float h0, l0, h1, l1;
                d2(acc[mf][nf][0] * alpha, h0, l0);
                d2(acc[mf][nf][1] * alpha, h1, l1);
                *(uint32_t*)(CH + (long)row * ldc + col) = pack2(h0, h1);
                *(uint32_t*)(CL + (long)row * ldc + col) = pack2(l0, l1);
                d2(acc[mf][nf][2] * alpha, h0, l0);
                d2(acc[mf][nf][3] * alpha, h1, l1);
                *(uint32_t*)(CH + (long)(row + 8) * ldc + col) = pack2(h0, h1);
                *(uint32_t*)(CL + (long)(row + 8) * ldc + col) = pack2(l0, l1);
            }
        }
    } else {
        constexpr int TSLD = BM + 4;
        float* ts = reinterpret_cast<float*>(smem);
        const int rl = wm * 32;
        const int cl = wn * WN;
#pragma unroll
        for (int mf = 0; mf < 2; mf++) {
            int row = rl + mf * 16 + (lane >> 2);
#pragma unroll
            for (int nf = 0; nf < NF; nf++) {
                int col = cl + nf * 8 + (lane & 3) * 2;
                ts[(col + 0) * TSLD + row]     = acc[mf][nf][0] * alpha;
                ts[(col + 1) * TSLD + row]     = acc[mf][nf][1] * alpha;
                ts[(col + 0) * TSLD + row + 8] = acc[mf][nf][2] * alpha;
                ts[(col + 1) * TSLD + row + 8] = acc[mf][nf][3] * alpha;
            }
        }
        __syncthreads();
        __nv_bfloat16* CH = Ch + (long)blockIdx.z * sC;
        __nv_bfloat16* CL = Cl + (long)blockIdx.z * sC;
#pragma unroll
        for (int rep = 0; rep < TN / 8; rep++) {
            int n = rep * 8 + wid;
            if (BM == 128) {
                float v0 = ts[n * TSLD + lane * 4 + 0];
                float v1 = ts[n * TSLD + lane * 4 + 1];
                float v2 = ts[n * TSLD + lane * 4 + 2];
                float v3 = ts[n * TSLD + lane * 4 + 3];
                float h0, l0, h1, l1, h2, l2, h3, l3;
                d2(v0, h0, l0); d2(v1, h1, l1); d2(v2, h2, l2); d2(v3, h3, l3);
                long o = (long)(n0 + n) * ldc + m0 + lane * 4;
                *(uint2*)(CH + o) = make_uint2(pack2(h0, h1), pack2(h2, h3));
                *(uint2*)(CL + o) = make_uint2(pack2(l0, l1), pack2(l2, l3));
            } else {
                float v0 = ts[n * TSLD + lane * 2 + 0];
                float v1 = ts[n * TSLD + lane * 2 + 1];
                float h0, l0, h1, l1;
                d2(v0, h0, l0); d2(v1, h1, l1);
                long o = (long)(n0 + n) * ldc + m0 + lane * 2;
                *(uint32_t*)(CH + o) = pack2(h0, h1);
                *(uint32_t*)(CL + o) = pack2(l0, l1);
            }
        }
    }
}

// ---------------------------------------------------------------------------
// Elementwise kernels
// ---------------------------------------------------------------------------
// fused rmsnorm + weight scale + hi/lo decomposition; one block per row of DD
__global__ void rmsdecomp(const float* __restrict__ X,
                          __nv_bfloat16* __restrict__ H, __nv_bfloat16* __restrict__ L,
                          const float* __restrict__ w) {
    long r = blockIdx.x;
    float4 v = ((const float4*)(X + r * DD))[threadIdx.x];
    float s = v.x * v.x + v.y * v.y + v.z * v.z + v.w * v.w;
    for (int o = 16; o; o >>= 1) s += __shfl_xor_sync(0xffffffffu, s, o);
    __shared__ float red[8];
    __shared__ float srs;
    if ((threadIdx.x & 31) == 0) red[threadIdx.x >> 5] = s;
    __syncthreads();
    if (threadIdx.x == 0) {
        float t = 0.f;
#pragma unroll
        for (int i = 0; i < 8; i++) t += red[i];
        srs = rsqrtf(t * (1.f / DD) + EPS_F);
    }
    __syncthreads();
    float rs = srs;
    float4 ww = ((const float4*)w)[threadIdx.x];
    float h0, h1, h2, h3, l0, l1, l2, l3;
    d2(v.x * rs * ww.x, h0, l0); d2(v.y * rs * ww.y, h1, l1);
    d2(v.z * rs * ww.z, h2, l2); d2(v.w * rs * ww.w, h3, l3);
    ((uint2*)H)[r * 256 + threadIdx.x] = make_uint2(pack2(h0, h1), pack2(h2, h3));
    ((uint2*)L)[r * 256 + threadIdx.x] = make_uint2(pack2(l0, l1), pack2(l2, l3));
}

__global__ void decomp4(const float* __restrict__ X,
                        __nv_bfloat16* __restrict__ H, __nv_bfloat16* __restrict__ L,
                        long n4) {
    long i = (long)blockIdx.x * blockDim.x + threadIdx.x;
    if (i >= n4) return;
    float4 v = ((const float4*)X)[i];
    float h0, h1, h2, h3, l0, l1, l2, l3;
    d2(v.x, h0, l0); d2(v.y, h1, l1); d2(v.z, h2, l2); d2(v.w, h3, l3);
    ((uint2*)H)[i] = make_uint2(pack2(h0, h1), pack2(h2, h3));
    ((uint2*)L)[i] = make_uint2(pack2(l0, l1), pack2(l2, l3));
}

__global__ void softmax64(float* __restrict__ S) {
    long idx = (long)blockIdx.x * blockDim.x + threadIdx.x;
    if (idx >= (long)NB * NM) return;
    float4* p = (float4*)(S + idx * NS);
    float4 v[16];
    float mx = -INFINITY;
#pragma unroll
    for (int i = 0; i < 16; i++) {
        v[i] = p[i];
        mx = fmaxf(mx, fmaxf(fmaxf(v[i].x, v[i].y), fmaxf(v[i].z, v[i].w)));
    }
    float sum = 0.f;
#pragma unroll
    for (int i = 0; i < 16; i++) {
        v[i].x = __expf(v[i].x - mx); v[i].y = __expf(v[i].y - mx);
        v[i].z = __expf(v[i].z - mx); v[i].w = __expf(v[i].w - mx);
        sum += v[i].x + v[i].y + v[i].z + v[i].w;
    }
    float inv = 1.f / sum;
#pragma unroll
    for (int i = 0; i < 16; i++) {
        v[i].x *= inv; v[i].y *= inv; v[i].z *= inv; v[i].w *= inv;
        p[i] = v[i];
    }
}

__global__ void renorm_tr(const float* __restrict__ S,
                          __nv_bfloat16* __restrict__ AH, __nv_bfloat16* __restrict__ AL) {
    int b = blockIdx.x >> 6, k = blockIdx.x & 63;
    const float* p = S + (long)b * NM * NS + k;
    float s = 0.f;
    for (int m = threadIdx.x; m < NM; m += 256) s += p[(long)m * NS];
    for (int o = 16; o; o >>= 1) s += __shfl_xor_sync(0xffffffffu, s, o);
    __shared__ float red[8];
    __shared__ float sinv;
    if ((threadIdx.x & 31) == 0) red[threadIdx.x >> 5] = s;
    __syncthreads();
    if (threadIdx.x == 0) {
        float t = 0.f;
#pragma unroll
        for (int i = 0; i < 8; i++) t += red[i];
        sinv = 1.f / (t + EPS_F);
    }
    __syncthreads();
    float inv = sinv;
    long ob = ((long)b * NS + k) * NM;
    for (int m = threadIdx.x; m < NM; m += 256) {
        float v = p[(long)m * NS] * inv;
        float h, l;
        d2(v, h, l);
        AH[ob + m] = __float2bfloat16_rn(h);
        AL[ob + m] = __float2bfloat16_rn(l);
    }
}

__global__ void gru_combine(const float* __restrict__ gcat,
                            float* __restrict__ slots,
                            __nv_bfloat16* __restrict__ SH, __nv_bfloat16* __restrict__ SL) {
    long i = (long)blockIdx.x * blockDim.x + threadIdx.x;
    if (i >= (long)NB * NS * DD) return;
    int r = (int)(i >> 10), c = (int)(i & 1023);
    long b3 = (long)r * 3 * DD + c;
    float xr = gcat[b3], xz = gcat[b3 + DD], xn = gcat[b3 + 2 * DD];
    float hr = gcat[G_OFF + b3], hz = gcat[G_OFF + b3 + DD], hn = gcat[G_OFF + b3 + 2 * DD];
    float rg = 1.f / (1.f + __expf(-(xr + hr)));
    float zg = 1.f / (1.f + __expf(-(xz + hz)));
    float ng = tanhf(xn + rg * hn);
    float o = (1.f - zg) * ng + zg * slots[i];
    slots[i] = o;
    float h, l;
    d2(o, h, l);
    SH[i] = __float2bfloat16_rn(h);
    SL[i] = __float2bfloat16_rn(l);
}

// ---------------------------------------------------------------------------
// Launch
// ---------------------------------------------------------------------------
extern "C" void kernel_launch(void* const* d_in, const int* in_sizes, int n_in,
                              void* d_out, int out_size)
{
    const float* slots_in = (const float*)d_in[0];
    const float* P        = (const float*)d_in[1];
    const float* Wq       = (const float*)d_in[2];
    const float* Wk       = (const float*)d_in[3];
    const float* Wv       = (const float*)d_in[4];
    const float* wih      = (const float*)d_in[5];
    const float* whh      = (const float*)d_in[6];
    const float* bih      = (const float*)d_in[7];
    const float* bhh      = (const float*)d_in[8];
    const float* snw      = (const float*)d_in[9];
    const float* inw      = (const float*)d_in[10];

    __nv_bfloat16 *pnh, *pnl, *kph, *kpl, *vth, *vtl;
    __nv_bfloat16 *wqh, *wql, *wkh, *wkl, *wvh, *wvl, *wch, *wcl;
    __nv_bfloat16 *ush, *usl, *snh, *snl, *qh, *ql, *ath, *atl;
    float *slots, *scT, *gcat, *bias2;
    cudaGetSymbolAddress((void**)&pnh, g_pnh);   cudaGetSymbolAddress((void**)&pnl, g_pnl);
    cudaGetSymbolAddress((void**)&kph, g_kph);   cudaGetSymbolAddress((void**)&kpl, g_kpl);
    cudaGetSymbolAddress((void**)&vth, g_vth);   cudaGetSymbolAddress((void**)&vtl, g_vtl);
    cudaGetSymbolAddress((void**)&wqh, g_wqh);   cudaGetSymbolAddress((void**)&wql, g_wql);
    cudaGetSymbolAddress((void**)&wkh, g_wkh);   cudaGetSymbolAddress((void**)&wkl, g_wkl);
    cudaGetSymbolAddress((void**)&wvh, g_wvh);   cudaGetSymbolAddress((void**)&wvl, g_wvl);
    cudaGetSymbolAddress((void**)&wch, g_wch);   cudaGetSymbolAddress((void**)&wcl, g_wcl);
    cudaGetSymbolAddress((void**)&ush, g_ush);   cudaGetSymbolAddress((void**)&usl, g_usl);
    cudaGetSymbolAddress((void**)&snh, g_snh);   cudaGetSymbolAddress((void**)&snl, g_snl);
    cudaGetSymbolAddress((void**)&qh, g_qh);     cudaGetSymbolAddress((void**)&ql, g_ql);
    cudaGetSymbolAddress((void**)&ath, g_ath);   cudaGetSymbolAddress((void**)&atl, g_atl);
    cudaGetSymbolAddress((void**)&slots, g_slots);
    cudaGetSymbolAddress((void**)&scT, g_scT);
    cudaGetSymbolAddress((void**)&gcat, g_gcat);
    cudaGetSymbolAddress((void**)&bias2, g_bias2);

    constexpr int SM_128_128 = (128 + 128) * 160 * 2;  // 81920
    constexpr int SM_128_64  = (128 + 64) * 160 * 2;   // 61440
    constexpr int SM_64_128  = (64 + 128) * 160 * 2;   // 61440
    constexpr int SM_64_64   = (64 + 64) * 160 * 2;    // 40960
    cudaFuncSetAttribute(mma_nt<128,128,1>, cudaFuncAttributeMaxDynamicSharedMemorySize, SM_128_128);
    cudaFuncSetAttribute(mma_nt<128,128,2>, cudaFuncAttributeMaxDynamicSharedMemorySize, SM_128_128);
    cudaFuncSetAttribute(mma_nt<128,64,0>,  cudaFuncAttributeMaxDynamicSharedMemorySize, SM_128_64);
    cudaFuncSetAttribute(mma_nt<64,128,0>,  cudaFuncAttributeMaxDynamicSharedMemorySize, SM_64_128);
    cudaFuncSetAttribute(mma_nt<64,64,1>,   cudaFuncAttributeMaxDynamicSharedMemorySize, SM_64_64);
    cudaFuncSetAttribute(mma_nt<64,64,2>,   cudaFuncAttributeMaxDynamicSharedMemorySize, SM_64_64);

    // ---- weight decomposition + packed GRU operands ----
    decomp4<<<DD * DD / 4 / 256, 256>>>(Wq, wqh, wql, DD * DD / 4);
    decomp4<<<DD * DD / 4 / 256, 256>>>(Wk, wkh, wkl, DD * DD / 4);
    decomp4<<<DD * DD / 4 / 256, 256>>>(Wv, wvh, wvl, DD * DD / 4);
    decomp4<<<3 * DD * DD / 4 / 256, 256>>>(wih, wch, wcl, 3 * DD * DD / 4);
    decomp4<<<3 * DD * DD / 4 / 256, 256>>>(whh, wch + W_OFF, wcl + W_OFF, 3 * DD * DD / 4);
    cudaMemcpyAsync(bias2, bih, 3 * DD * sizeof(float), cudaMemcpyDeviceToDevice, 0);
    cudaMemcpyAsync(bias2 + 3 * DD, bhh, 3 * DD * sizeof(float), cudaMemcpyDeviceToDevice, 0);

    cudaMemcpyAsync(slots, slots_in, (size_t)NB * NS * DD * sizeof(float),
                    cudaMemcpyDeviceToDevice, 0);
    decomp4<<<NB * NS * DD / 4 / 256, 256>>>(slots, ush + U_OFF, usl + U_OFF, NB * NS * DD / 4);

    // ---- Pn = rmsnorm(P)*w (fused) ----
    rmsdecomp<<<NB * NM, 256>>>(P, pnh, pnl, inw);

    // ---- K/V projections ----
    mma_nt<128,128,1><<<dim3(DD / 128, NB * NM / 128, 1), 256, SM_128_128>>>(
        pnh, pnl, DD, 0, wkh, wkl, DD, 0,
        nullptr, kph, kpl, DD, 0, DD, nullptr, 0, 1.f);
    mma_nt<128,128,2><<<dim3(DD / 128, NB * NM / 128, 1), 256, SM_128_128>>>(
        pnh, pnl, DD, 0, wvh, wvl, DD, 0,
        nullptr, vth, vtl, (long)NB * NM, 0, DD, nullptr, 0, 1.f);

    for (int it = 0; it < 3; it++) {
        // slot rmsnorm + decomposition (fused)
        rmsdecomp<<<NB * NS, 256>>>(slots, snh, snl, snw);

        // q = sn @ Wq^T  (BM=64 for occupancy: 128 CTAs)
        mma_nt<64,64,1><<<dim3(DD / 64, NB * NS / 64, 1), 256, SM_64_64>>>(
            snh, snl, DD, 0, wqh, wql, DD, 0,
            nullptr, qh, ql, DD, 0, DD, nullptr, 0, 1.f);

        // scoresT[b][m][k] = SCALE * kproj[b] @ q[b]^T
        mma_nt<128,64,0><<<dim3(1, NM / 128, NB), 256, SM_128_64>>>(
            kph, kpl, DD, (long)NM * DD, qh, ql, DD, (long)NS * DD,
            scT, nullptr, nullptr, NS, (long)NM * NS, DD, nullptr, 0, SCALE_F);

        softmax64<<<NB * NM / 256, 256>>>(scT);
        renorm_tr<<<NB * NS, 256>>>(scT, ath, atl);

        // updates[b][k][d] = (vprojT[b] @ attn[b]^T)^T  -> packed slot 0 of ush
        mma_nt<64,64,2><<<dim3(1, DD / 64, NB), 256, SM_64_64>>>(
            vth, vtl, (long)NB * NM, NM, ath, atl, NM, (long)NS * NM,
            nullptr, ush, usl, DD, (long)NS * DD, NM, nullptr, 0, 1.f);

        // GRU gates: batched z=2 ([0]: u@wih^T+bih, [1]: s@whh^T+bhh)
        mma_nt<64,128,0><<<dim3(3 * DD / 128, NB * NS / 64, 2), 256, SM_64_128>>>(
            ush, usl, DD, U_OFF, wch, wcl, DD, W_OFF,
            gcat, nullptr, nullptr, 3 * DD, G_OFF, DD, bias2, 3 * DD, 1.f);

        gru_combine<<<NB * NS * DD / 256, 256>>>(gcat, slots, ush + U_OFF, usl + U_OFF);
    }

    cudaMemcpyAsync(d_out, slots, (size_t)NB * NS * DD * sizeof(float),
                    cudaMemcpyDeviceToDevice, 0);
}